// round 4
// baseline (speedup 1.0000x reference)
#include <cuda_runtime.h>
#include <cstdint>

// YOLOv1 loss: pred [4096,14,14,30] fp32, target same, output scalar fp32.
// R4: 2-stage double-buffered cp.async pipeline. TILE_C=98 (divides 802816
// exactly -> 8192 tiles), 2x2x98x30x4 = 47040 B static smem (<48K limit).
// Loads for tile k+1 issued before computing tile k -> DMA never idles.

#define S_GRID   14
#define NBATCH   4096
#define NCH      30
#define NCELLS   (NBATCH * S_GRID * S_GRID)   // 802816
#define TILE_C   98
#define NTILES   (NCELLS / TILE_C)            // 8192 exact
#define BLOCK    128
#define TILE_F4  ((TILE_C * NCH) / 4)         // 735 float4 per array per tile
#define CP_TOTAL (2 * TILE_F4)                // 1470 copies per tile
#define CP_ITERS ((CP_TOTAL + BLOCK - 1) / BLOCK)  // 12
#define STAGE_F  (TILE_C * NCH)               // 2940 floats per stage
#define GRID_N   592                          // 4 blocks/SM * 148 SMs

__global__ void yolo_zero_out(float* out) {
    if (threadIdx.x == 0) out[0] = 0.0f;
}

__device__ __forceinline__ void cp_async16(uint32_t smem_dst, const void* gsrc) {
    asm volatile("cp.async.cg.shared.global [%0], [%1], 16;\n"
                 :: "r"(smem_dst), "l"(gsrc));
}

__device__ __forceinline__ void prefetch_tile(
    int tile, int stage, uint32_t sp_base, uint32_t st_base,
    const float4* __restrict__ pred4, const float4* __restrict__ tgt4)
{
    const int base4 = tile * TILE_F4;
    const uint32_t soff = (uint32_t)stage * (STAGE_F * 4u);
    #pragma unroll
    for (int k = 0; k < CP_ITERS; k++) {
        const int j = threadIdx.x + k * BLOCK;
        if (j < TILE_F4) {
            cp_async16(sp_base + soff + (uint32_t)j * 16u, pred4 + base4 + j);
        } else if (j < CP_TOTAL) {
            const int i = j - TILE_F4;
            cp_async16(st_base + soff + (uint32_t)i * 16u, tgt4 + base4 + i);
        }
    }
    asm volatile("cp.async.commit_group;\n" ::: "memory");
}

__global__ __launch_bounds__(BLOCK)
void yolo_loss_kernel(const float4* __restrict__ pred4,
                      const float4* __restrict__ tgt4,
                      float* __restrict__ out)
{
    __shared__ float sp[2][STAGE_F];   // 23520 B
    __shared__ float st[2][STAGE_F];   // 23520 B
    __shared__ float wsum[BLOCK / 32];

    const uint32_t sp_base = (uint32_t)__cvta_generic_to_shared(&sp[0][0]);
    const uint32_t st_base = (uint32_t)__cvta_generic_to_shared(&st[0][0]);

    const float invS = 1.0f / 14.0f;
    float acc = 0.0f;

    int tile = blockIdx.x;
    int stage = 0;
    // prologue: every block has >= 13 tiles, so this is always valid
    prefetch_tile(tile, 0, sp_base, st_base, pred4, tgt4);

    for (; tile < NTILES; tile += GRID_N) {
        const int next = tile + GRID_N;
        const bool has_next = next < NTILES;
        if (has_next)
            prefetch_tile(next, stage ^ 1, sp_base, st_base, pred4, tgt4);

        if (has_next)
            asm volatile("cp.async.wait_group 1;\n" ::: "memory");
        else
            asm volatile("cp.async.wait_group 0;\n" ::: "memory");
        __syncthreads();

        if (threadIdx.x < TILE_C) {
            const float* p = &sp[stage][0] + threadIdx.x * NCH;
            const float* t = &st[stage][0] + threadIdx.x * NCH;

            // target box 0 (boxes are tiled identical in target)
            const float t0x = t[0], t0y = t[1], t0w = t[2], t0h = t[3];
            const float tobj = t[4];
            const float of = (tobj > 0.0f) ? 1.0f : 0.0f;

            const float tcx = t0x * invS, tcy = t0y * invS;
            const float thw = 0.5f * t0w, thh = 0.5f * t0h;
            const float tx0 = tcx - thw, tx1 = tcx + thw;
            const float ty0 = tcy - thh, ty1 = tcy + thh;
            const float area_t = t0w * t0h;

            float iou[2], px[2], py[2], pw[2], ph[2], pc[2];
            #pragma unroll
            for (int b = 0; b < 2; b++) {
                px[b] = p[5*b + 0]; py[b] = p[5*b + 1];
                pw[b] = p[5*b + 2]; ph[b] = p[5*b + 3];
                pc[b] = p[5*b + 4];
                const float pcx = px[b] * invS, pcy = py[b] * invS;
                const float phw = 0.5f * pw[b], phh = 0.5f * ph[b];
                const float px0 = pcx - phw, px1 = pcx + phw;
                const float py0 = pcy - phh, py1 = pcy + phh;
                const float ltx = fmaxf(px0, tx0), lty = fmaxf(py0, ty0);
                const float rbx = fminf(px1, tx1), rby = fminf(py1, ty1);
                const float wi = fmaxf(rbx - ltx, 0.0f);
                const float hi = fmaxf(rby - lty, 0.0f);
                const float inter = wi * hi;
                const float area_p = pw[b] * ph[b];
                iou[b] = inter / (area_p + area_t - inter);
            }

            // argmax over 2 boxes; ties -> box 0 (matches jnp.argmax)
            const int b = (iou[1] > iou[0]) ? 1 : 0;
            const float max_iou = fmaxf(iou[0], iou[1]);

            const float dx = px[b] - t0x, dy = py[b] - t0y;
            const float lxy = dx*dx + dy*dy;
            const float dw = sqrtf(pw[b]) - sqrtf(t0w);
            const float dh = sqrtf(ph[b]) - sqrtf(t0h);
            const float lwh = dw*dw + dh*dh;
            const float dob = pc[b] - max_iou;
            const float lobj = dob * dob;
            const float lno = pc[0]*pc[0] + pc[1]*pc[1]; // target conf=0 when no obj

            float lcls = 0.0f;
            #pragma unroll
            for (int c = 0; c < 20; c++) {
                const float d = p[10 + c] - t[10 + c];
                lcls += d * d;
            }

            acc += of * (5.0f * (lxy + lwh) + lobj + lcls)
                 + (1.0f - of) * (0.5f * lno);
        }
        __syncthreads();   // compute done before this buffer is refilled
        stage ^= 1;
    }

    acc *= (1.0f / (float)NBATCH);

    // warp reduce
    #pragma unroll
    for (int o = 16; o > 0; o >>= 1)
        acc += __shfl_down_sync(0xffffffffu, acc, o);
    if ((threadIdx.x & 31) == 0) wsum[threadIdx.x >> 5] = acc;
    __syncthreads();
    if (threadIdx.x == 0) {
        float s = 0.0f;
        #pragma unroll
        for (int w = 0; w < BLOCK / 32; w++) s += wsum[w];
        atomicAdd(out, s);
    }
}

extern "C" void kernel_launch(void* const* d_in, const int* in_sizes, int n_in,
                              void* d_out, int out_size)
{
    const float4* pred4 = (const float4*)d_in[0];
    const float4* tgt4  = (const float4*)d_in[1];
    float* out = (float*)d_out;

    yolo_zero_out<<<1, 32>>>(out);
    yolo_loss_kernel<<<GRID_N, BLOCK>>>(pred4, tgt4, out);
}

// round 5
// speedup vs baseline: 1.0469x; 1.0469x over previous
#include <cuda_runtime.h>
#include <cstdint>

// YOLOv1 loss: pred [4096,14,14,30] fp32, target same, output scalar fp32.
// R5: cp.async.bulk (TMA-style DMA) + mbarrier 3-stage ring in DYNAMIC smem.
// One bulk copy per array per tile (15360B each) -> no per-thread copy loops,
// no LDGSTS issue bottleneck. 92KB/block, 2 blocks/SM, ~123KB/SM in flight.

#define NBATCH     4096
#define NCH        30
#define NCELLS     (NBATCH * 14 * 14)          // 802816
#define TILE_C     128
#define NTILES     (NCELLS / TILE_C)           // 6272 exact
#define BLOCK      128
#define NSTAGE     3
#define ARR_BYTES  (TILE_C * NCH * 4)          // 15360 B per array
#define STAGE_BYTES (2 * ARR_BYTES)            // 30720 B (pred+tgt)
#define STAGE_F    (STAGE_BYTES / 4)           // 7680 floats
#define SMEM_DYN   (NSTAGE * STAGE_BYTES)      // 92160 B
#define GRID_N     296                         // 2 blocks/SM * 148 SMs

__global__ void yolo_zero_out(float* out) {
    if (threadIdx.x == 0) out[0] = 0.0f;
}

__device__ __forceinline__ void mbar_init(uint32_t mbar, uint32_t count) {
    asm volatile("mbarrier.init.shared.b64 [%0], %1;"
                 :: "r"(mbar), "r"(count) : "memory");
}
__device__ __forceinline__ void mbar_expect_tx(uint32_t mbar, uint32_t bytes) {
    asm volatile("mbarrier.arrive.expect_tx.shared.b64 _, [%0], %1;"
                 :: "r"(mbar), "r"(bytes) : "memory");
}
__device__ __forceinline__ void bulk_g2s(uint32_t dst, const void* src,
                                         uint32_t bytes, uint32_t mbar) {
    asm volatile(
        "cp.async.bulk.shared::cluster.global.mbarrier::complete_tx::bytes "
        "[%0], [%1], %2, [%3];"
        :: "r"(dst), "l"(src), "r"(bytes), "r"(mbar) : "memory");
}
__device__ __forceinline__ void mbar_wait(uint32_t mbar, uint32_t parity) {
    asm volatile(
        "{\n\t"
        ".reg .pred P;\n\t"
        "LW%=:\n\t"
        "mbarrier.try_wait.parity.acquire.cta.shared::cta.b64 P, [%0], %1, 0x989680;\n\t"
        "@P bra LD%=;\n\t"
        "bra LW%=;\n\t"
        "LD%=:\n\t"
        "}"
        :: "r"(mbar), "r"(parity) : "memory");
}

extern __shared__ float dynbuf[];

__global__ __launch_bounds__(BLOCK)
void yolo_loss_kernel(const float* __restrict__ pred,
                      const float* __restrict__ tgt,
                      float* __restrict__ out)
{
    __shared__ uint64_t mbar_s[NSTAGE];
    __shared__ float wsum[BLOCK / 32];

    const uint32_t smem_base = (uint32_t)__cvta_generic_to_shared(dynbuf);
    const uint32_t mbar0 = (uint32_t)__cvta_generic_to_shared(mbar_s);

    if (threadIdx.x == 0) {
        #pragma unroll
        for (int s = 0; s < NSTAGE; s++) mbar_init(mbar0 + 8u * s, 1);
    }
    __syncthreads();

    // this block's tile count: tiles are blockIdx.x, +GRID_N, ...
    const int n = (NTILES - blockIdx.x + GRID_N - 1) / GRID_N;   // 21 or 22

    // issue tile i into stage i%NSTAGE
    auto issue = [&](int i) {
        const int tile = blockIdx.x + i * GRID_N;
        const int s = i % NSTAGE;
        const uint32_t mb = mbar0 + 8u * s;
        const uint32_t dst = smem_base + (uint32_t)s * STAGE_BYTES;
        mbar_expect_tx(mb, STAGE_BYTES);
        bulk_g2s(dst,             pred + (size_t)tile * (TILE_C * NCH), ARR_BYTES, mb);
        bulk_g2s(dst + ARR_BYTES, tgt  + (size_t)tile * (TILE_C * NCH), ARR_BYTES, mb);
    };

    // prologue: prefetch depth 2
    if (threadIdx.x == 0) {
        if (n > 0) issue(0);
        if (n > 1) issue(1);
    }

    const float invS = 1.0f / 14.0f;
    float acc = 0.0f;

    for (int i = 0; i < n; i++) {
        // refill stage (i+2)%NSTAGE: its previous tile (i-1) finished at the
        // __syncthreads() that ended iteration i-1.
        if (threadIdx.x == 0 && (i + 2) < n) issue(i + 2);

        const int s = i % NSTAGE;
        mbar_wait(mbar0 + 8u * s, (uint32_t)((i / NSTAGE) & 1));

        {
            const float* p = dynbuf + s * STAGE_F + threadIdx.x * NCH;
            const float* t = p + (ARR_BYTES / 4);

            // target box 0 (boxes are tiled identical in target)
            const float t0x = t[0], t0y = t[1], t0w = t[2], t0h = t[3];
            const float tobj = t[4];
            const float of = (tobj > 0.0f) ? 1.0f : 0.0f;

            const float tcx = t0x * invS, tcy = t0y * invS;
            const float thw = 0.5f * t0w, thh = 0.5f * t0h;
            const float tx0 = tcx - thw, tx1 = tcx + thw;
            const float ty0 = tcy - thh, ty1 = tcy + thh;
            const float area_t = t0w * t0h;

            float iou[2], px[2], py[2], pw[2], ph[2], pc[2];
            #pragma unroll
            for (int b = 0; b < 2; b++) {
                px[b] = p[5*b + 0]; py[b] = p[5*b + 1];
                pw[b] = p[5*b + 2]; ph[b] = p[5*b + 3];
                pc[b] = p[5*b + 4];
                const float pcx = px[b] * invS, pcy = py[b] * invS;
                const float phw = 0.5f * pw[b], phh = 0.5f * ph[b];
                const float px0 = pcx - phw, px1 = pcx + phw;
                const float py0 = pcy - phh, py1 = pcy + phh;
                const float ltx = fmaxf(px0, tx0), lty = fmaxf(py0, ty0);
                const float rbx = fminf(px1, tx1), rby = fminf(py1, ty1);
                const float wi = fmaxf(rbx - ltx, 0.0f);
                const float hi = fmaxf(rby - lty, 0.0f);
                const float inter = wi * hi;
                const float area_p = pw[b] * ph[b];
                iou[b] = inter / (area_p + area_t - inter);
            }

            // argmax over 2 boxes; ties -> box 0 (matches jnp.argmax)
            const int b = (iou[1] > iou[0]) ? 1 : 0;
            const float max_iou = fmaxf(iou[0], iou[1]);

            const float dx = px[b] - t0x, dy = py[b] - t0y;
            const float lxy = dx*dx + dy*dy;
            const float dw = sqrtf(pw[b]) - sqrtf(t0w);
            const float dh = sqrtf(ph[b]) - sqrtf(t0h);
            const float lwh = dw*dw + dh*dh;
            const float dob = pc[b] - max_iou;
            const float lobj = dob * dob;
            const float lno = pc[0]*pc[0] + pc[1]*pc[1]; // tgt conf=0 when no obj

            float lcls = 0.0f;
            #pragma unroll
            for (int c = 0; c < 20; c++) {
                const float d = p[10 + c] - t[10 + c];
                lcls += d * d;
            }

            acc += of * (5.0f * (lxy + lwh) + lobj + lcls)
                 + (1.0f - of) * (0.5f * lno);
        }
        __syncthreads();   // all readers done before stage is refilled
    }

    acc *= (1.0f / (float)NBATCH);

    // warp reduce
    #pragma unroll
    for (int o = 16; o > 0; o >>= 1)
        acc += __shfl_down_sync(0xffffffffu, acc, o);
    if ((threadIdx.x & 31) == 0) wsum[threadIdx.x >> 5] = acc;
    __syncthreads();
    if (threadIdx.x == 0) {
        float s = 0.0f;
        #pragma unroll
        for (int w = 0; w < BLOCK / 32; w++) s += wsum[w];
        atomicAdd(out, s);
    }
}

extern "C" void kernel_launch(void* const* d_in, const int* in_sizes, int n_in,
                              void* d_out, int out_size)
{
    const float* pred = (const float*)d_in[0];
    const float* tgt  = (const float*)d_in[1];
    float* out = (float*)d_out;

    cudaFuncSetAttribute(yolo_loss_kernel,
                         cudaFuncAttributeMaxDynamicSharedMemorySize, SMEM_DYN);

    yolo_zero_out<<<1, 32>>>(out);
    yolo_loss_kernel<<<GRID_N, BLOCK, SMEM_DYN>>>(pred, tgt, out);
}